// round 4
// baseline (speedup 1.0000x reference)
#include <cuda_runtime.h>
#include <math.h>

// Problem constants (fixed by the dataset instance)
#define B_SZ    4096
#define D_SZ    768
#define HID_SZ  256
#define NC_SZ   200
#define NOLD_SZ 100
#define NNEW_SZ 100
#define EPSILONF 0.05f
#define INV_TAU  10.0f
#define EPSF     1e-8f

// ---------------- device scratch (static: no allocations allowed) -------------
__device__ float g_znorm[B_SZ * D_SZ];
__device__ float g_bnorm[B_SZ * D_SZ];
__device__ float g_f1z[B_SZ * HID_SZ];
__device__ float g_f2z[B_SZ * HID_SZ];
__device__ float g_sim[(size_t)B_SZ * B_SZ];
__device__ float g_attn[(size_t)B_SZ * B_SZ];
__device__ unsigned char g_mask[(size_t)B_SZ * B_SZ];
__device__ float g_meanprobs[NC_SZ];
__device__ float g_losssum;
__device__ float g_nvalid;

// ---------------- init ---------------------------------------------------------
__global__ void zero_kernel() {
    int t = threadIdx.x;
    if (t < NC_SZ) g_meanprobs[t] = 0.f;
    if (t == 0) { g_losssum = 0.f; g_nvalid = 0.f; }
}

// ---------------- entropy stats: mean softmax probs over all rows --------------
// active = concat(arange(100), arange(100,200)) == arange(200): gather is identity.
// One warp per row; 8 warps per block.
__global__ void entropy_kernel(const float* __restrict__ logits) {
    __shared__ float sp[NC_SZ];
    int tid = threadIdx.x;
    for (int c = tid; c < NC_SZ; c += blockDim.x) sp[c] = 0.f;
    __syncthreads();

    int warp = tid >> 5, lane = tid & 31;
    int row = blockIdx.x * 8 + warp;
    const float* lrow = logits + (size_t)row * NC_SZ;

    float v[7];
    int cnt = 0;
    float m = -1e30f;
    for (int c = lane; c < NC_SZ; c += 32) {
        float x = lrow[c];
        v[cnt++] = x;
        m = fmaxf(m, x);
    }
#pragma unroll
    for (int o = 16; o > 0; o >>= 1)
        m = fmaxf(m, __shfl_xor_sync(0xffffffffu, m, o));
    float s = 0.f;
    for (int i = 0; i < cnt; i++) { v[i] = __expf(v[i] - m); s += v[i]; }
#pragma unroll
    for (int o = 16; o > 0; o >>= 1)
        s += __shfl_xor_sync(0xffffffffu, s, o);
    float inv = 1.f / s;
    int k = 0;
    for (int c = lane; c < NC_SZ; c += 32)
        atomicAdd(&sp[c], v[k++] * inv);
    __syncthreads();
    for (int c = tid; c < NC_SZ; c += blockDim.x)
        atomicAdd(&g_meanprobs[c], sp[c]);
}

// ---------------- row L2 normalize (z_u -> g_znorm, base -> g_bnorm) -----------
__global__ void normalize_kernel(const float* __restrict__ zu,
                                 const float* __restrict__ bf) {
    int row = blockIdx.x;
    const float* src = (blockIdx.y == 0) ? zu : bf;
    float* dst = (blockIdx.y == 0) ? g_znorm : g_bnorm;
    const float* srow = src + (size_t)row * D_SZ;
    float* drow = dst + (size_t)row * D_SZ;

    float ss = 0.f;
    for (int k = threadIdx.x; k < D_SZ; k += blockDim.x) {
        float x = srow[k];
        ss = fmaf(x, x, ss);
    }
    __shared__ float red[8];
    __shared__ float s_inv;
    int lane = threadIdx.x & 31, w = threadIdx.x >> 5;
#pragma unroll
    for (int o = 16; o > 0; o >>= 1)
        ss += __shfl_xor_sync(0xffffffffu, ss, o);
    if (lane == 0) red[w] = ss;
    __syncthreads();
    if (threadIdx.x == 0) {
        float t = 0.f;
#pragma unroll
        for (int i = 0; i < 8; i++) t += red[i];
        float nn = fmaxf(sqrtf(t), 1e-12f);
        s_inv = 1.f / nn;
    }
    __syncthreads();
    float inv = s_inv;
    for (int k = threadIdx.x; k < D_SZ; k += blockDim.x)
        drow[k] = srow[k] * inv;
}

// ---------------- generic C = A * B^T  (A: MxK, B: NxK, both row-major) --------
// 128x128 block tile, 8x8 microtile, BK=8, 256 threads.
// mode 0: Cf[i*N+j] = acc            (sim / attn)
// mode 1: Cmask[i*N+j] = (acc > 0.05f && i != j)   (packed as bytes)
// mode 2: Cf[i*N+j] = acc + bias[j]  (f1_z / f2_z)
__global__ void __launch_bounds__(256, 2)
gemm_nt(const float* __restrict__ A, const float* __restrict__ Bm,
        float* __restrict__ Cf, unsigned char* __restrict__ Cmask,
        const float* __restrict__ bias, int N, int K, int mode) {
    __shared__ __align__(16) float As[8][128];
    __shared__ __align__(16) float Bs[8][128];

    const int tid = threadIdx.x;
    const int tx = tid & 15;
    const int ty = tid >> 4;
    const int rowBase = blockIdx.y * 128;
    const int colBase = blockIdx.x * 128;

    const int lrow = tid >> 1;
    const int lc4 = (tid & 1) * 4;
    const float* Ap = A + (size_t)(rowBase + lrow) * K + lc4;
    const float* Bp = Bm + (size_t)(colBase + lrow) * K + lc4;

    float acc[8][8];
#pragma unroll
    for (int r = 0; r < 8; r++)
#pragma unroll
        for (int c = 0; c < 8; c++) acc[r][c] = 0.f;

    for (int k0 = 0; k0 < K; k0 += 8) {
        float4 av = *(const float4*)(Ap + k0);
        float4 bv = *(const float4*)(Bp + k0);
        As[lc4 + 0][lrow] = av.x; As[lc4 + 1][lrow] = av.y;
        As[lc4 + 2][lrow] = av.z; As[lc4 + 3][lrow] = av.w;
        Bs[lc4 + 0][lrow] = bv.x; Bs[lc4 + 1][lrow] = bv.y;
        Bs[lc4 + 2][lrow] = bv.z; Bs[lc4 + 3][lrow] = bv.w;
        __syncthreads();
#pragma unroll
        for (int kk = 0; kk < 8; kk++) {
            float4 a0 = *(const float4*)&As[kk][ty * 8];
            float4 a1 = *(const float4*)&As[kk][ty * 8 + 4];
            float4 b0 = *(const float4*)&Bs[kk][tx * 8];
            float4 b1 = *(const float4*)&Bs[kk][tx * 8 + 4];
            float ar[8] = {a0.x, a0.y, a0.z, a0.w, a1.x, a1.y, a1.z, a1.w};
            float bc[8] = {b0.x, b0.y, b0.z, b0.w, b1.x, b1.y, b1.z, b1.w};
#pragma unroll
            for (int r = 0; r < 8; r++)
#pragma unroll
                for (int c = 0; c < 8; c++)
                    acc[r][c] = fmaf(ar[r], bc[c], acc[r][c]);
        }
        __syncthreads();
    }

    const int r0 = rowBase + ty * 8;
    const int c0 = colBase + tx * 8;
    if (mode == 0) {
#pragma unroll
        for (int r = 0; r < 8; r++) {
            float* dst = Cf + (size_t)(r0 + r) * N + c0;
            *(float4*)dst = make_float4(acc[r][0], acc[r][1], acc[r][2], acc[r][3]);
            *(float4*)(dst + 4) = make_float4(acc[r][4], acc[r][5], acc[r][6], acc[r][7]);
        }
    } else if (mode == 1) {
#pragma unroll
        for (int r = 0; r < 8; r++) {
            int i = r0 + r;
            unsigned int w0 = 0, w1 = 0;
#pragma unroll
            for (int c = 0; c < 4; c++)
                if (acc[r][c] > EPSILONF && i != (c0 + c)) w0 |= (1u << (8 * c));
#pragma unroll
            for (int c = 4; c < 8; c++)
                if (acc[r][c] > EPSILONF && i != (c0 + c)) w1 |= (1u << (8 * (c - 4)));
            unsigned int* dst = (unsigned int*)(Cmask + (size_t)i * N + c0);
            dst[0] = w0;
            dst[1] = w1;
        }
    } else {
        float bv0[8];
#pragma unroll
        for (int c = 0; c < 8; c++) bv0[c] = bias[c0 + c];
#pragma unroll
        for (int r = 0; r < 8; r++) {
            float* dst = Cf + (size_t)(r0 + r) * N + c0;
            *(float4*)dst = make_float4(acc[r][0] + bv0[0], acc[r][1] + bv0[1],
                                        acc[r][2] + bv0[2], acc[r][3] + bv0[3]);
            *(float4*)(dst + 4) = make_float4(acc[r][4] + bv0[4], acc[r][5] + bv0[5],
                                              acc[r][6] + bv0[6], acc[r][7] + bv0[7]);
        }
    }
}

// ---------------- per-row loss: denom sum + masked online softmax --------------
// loss_i = log(denom + eps) - (sum_w sim)/tau   (sum of masked softmax weights == 1)
__global__ void row_loss_kernel() {
    int i = blockIdx.x;
    const float* srow = g_sim + (size_t)i * B_SZ;
    const float* arow = g_attn + (size_t)i * B_SZ;
    const unsigned char* mrow = g_mask + (size_t)i * B_SZ;

    float den = 0.f, m = -1e30f, Z = 0.f, T = 0.f, n = 0.f;
    for (int j = threadIdx.x; j < B_SZ; j += blockDim.x) {
        float s = srow[j];
        if (j != i) den += __expf(s * INV_TAU);
        if (mrow[j]) {
            n += 1.0f;
            float a = arow[j];
            if (a > m) {
                float sc = __expf(m - a);
                Z *= sc; T *= sc; m = a;
            }
            float e = __expf(a - m);
            Z += e;
            T += e * s;
        }
    }

    int lane = threadIdx.x & 31, w = threadIdx.x >> 5;
#pragma unroll
    for (int o = 16; o > 0; o >>= 1) {
        float m2 = __shfl_down_sync(0xffffffffu, m, o);
        float Z2 = __shfl_down_sync(0xffffffffu, Z, o);
        float T2 = __shfl_down_sync(0xffffffffu, T, o);
        float d2 = __shfl_down_sync(0xffffffffu, den, o);
        float n2 = __shfl_down_sync(0xffffffffu, n, o);
        float M = fmaxf(m, m2);
        float s1 = __expf(m - M), s2 = __expf(m2 - M);
        Z = Z * s1 + Z2 * s2;
        T = T * s1 + T2 * s2;
        m = M;
        den += d2;
        n += n2;
    }
    __shared__ float sm_[8], sZ_[8], sT_[8], sd_[8], sn_[8];
    if (lane == 0) { sm_[w] = m; sZ_[w] = Z; sT_[w] = T; sd_[w] = den; sn_[w] = n; }
    __syncthreads();
    if (w == 0) {
        if (lane < 8) { m = sm_[lane]; Z = sZ_[lane]; T = sT_[lane]; den = sd_[lane]; n = sn_[lane]; }
        else { m = -1e30f; Z = 0.f; T = 0.f; den = 0.f; n = 0.f; }
#pragma unroll
        for (int o = 4; o > 0; o >>= 1) {
            float m2 = __shfl_down_sync(0xffffffffu, m, o);
            float Z2 = __shfl_down_sync(0xffffffffu, Z, o);
            float T2 = __shfl_down_sync(0xffffffffu, T, o);
            float d2 = __shfl_down_sync(0xffffffffu, den, o);
            float n2 = __shfl_down_sync(0xffffffffu, n, o);
            float M = fmaxf(m, m2);
            float s1 = __expf(m - M), s2 = __expf(m2 - M);
            Z = Z * s1 + Z2 * s2;
            T = T * s1 + T2 * s2;
            m = M;
            den += d2;
            n += n2;
        }
        if (lane == 0 && n > 0.5f) {
            float loss_i = logf(den + EPSF) - (T / Z) * INV_TAU;
            atomicAdd(&g_losssum, loss_i / n);
            atomicAdd(&g_nvalid, 1.0f);
        }
    }
}

// ---------------- finalize: entropy terms + contrastive mean -------------------
__global__ void finalize_kernel(float* out) {
    const double invB = 1.0 / (double)B_SZ;
    double pold = 0.0, pnew = 0.0;
    for (int c = 0; c < NOLD_SZ; c++) pold += (double)g_meanprobs[c] * invB;
    for (int c = NOLD_SZ; c < NC_SZ; c++) pnew += (double)g_meanprobs[c] * invB;
    double loss_inter = pold * log(pold + 1e-8) + pnew * log(pnew + 1e-8) + log(2.0);
    double lo = 0.0;
    for (int c = 0; c < NOLD_SZ; c++) {
        double q = ((double)g_meanprobs[c] * invB) / (pold + 1e-8);
        lo += q * log(q + 1e-8);
    }
    lo += log((double)NOLD_SZ);
    double ln_ = 0.0;
    for (int c = NOLD_SZ; c < NC_SZ; c++) {
        double q = ((double)g_meanprobs[c] * invB) / (pnew + 1e-8);
        ln_ += q * log(q + 1e-8);
    }
    ln_ += log((double)NNEW_SZ);
    double le = loss_inter + lo + ln_;

    float nv = g_nvalid;
    float lc = (nv > 0.f) ? (g_losssum / fmaxf(nv, 1.0f)) : 0.f;
    out[0] = (float)le + lc;
}

// ---------------- launch --------------------------------------------------------
extern "C" void kernel_launch(void* const* d_in, const int* in_sizes, int n_in,
                              void* d_out, int out_size) {
    const float* z_u    = (const float*)d_in[0];
    const float* logits = (const float*)d_in[1];
    // d_in[2], d_in[3]: old/new class index arrays == arange(200) (identity gather)
    const float* base   = (const float*)d_in[4];
    const float* f1w    = (const float*)d_in[5];
    const float* f1b    = (const float*)d_in[6];
    const float* f2w    = (const float*)d_in[7];
    const float* f2b    = (const float*)d_in[8];
    float* out = (float*)d_out;
    (void)in_sizes; (void)n_in; (void)out_size;

    void *pz, *pb, *p1, *p2, *ps, *pa, *pm;
    cudaGetSymbolAddress(&pz, g_znorm);
    cudaGetSymbolAddress(&pb, g_bnorm);
    cudaGetSymbolAddress(&p1, g_f1z);
    cudaGetSymbolAddress(&p2, g_f2z);
    cudaGetSymbolAddress(&ps, g_sim);
    cudaGetSymbolAddress(&pa, g_attn);
    cudaGetSymbolAddress(&pm, g_mask);

    zero_kernel<<<1, 256>>>();
    entropy_kernel<<<B_SZ / 8, 256>>>(logits);
    normalize_kernel<<<dim3(B_SZ, 2), 256>>>(z_u, base);

    // f1_z / f2_z projections: [4096 x 256] = z_u[4096x768] @ w^T + b
    gemm_nt<<<dim3(HID_SZ / 128, B_SZ / 128), 256>>>(
        z_u, f1w, (float*)p1, nullptr, f1b, HID_SZ, D_SZ, 2);
    gemm_nt<<<dim3(HID_SZ / 128, B_SZ / 128), 256>>>(
        z_u, f2w, (float*)p2, nullptr, f2b, HID_SZ, D_SZ, 2);

    // sim = z_norm @ z_norm^T
    gemm_nt<<<dim3(B_SZ / 128, B_SZ / 128), 256>>>(
        (float*)pz, (float*)pz, (float*)ps, nullptr, nullptr, B_SZ, D_SZ, 0);
    // mask = (base_norm @ base_norm^T > 0.05) & ~eye  (bytes)
    gemm_nt<<<dim3(B_SZ / 128, B_SZ / 128), 256>>>(
        (float*)pb, (float*)pb, nullptr, (unsigned char*)pm, nullptr, B_SZ, D_SZ, 1);
    // attn = f1_z @ f2_z^T
    gemm_nt<<<dim3(B_SZ / 128, B_SZ / 128), 256>>>(
        (float*)p1, (float*)p2, (float*)pa, nullptr, nullptr, B_SZ, HID_SZ, 0);

    row_loss_kernel<<<B_SZ, 256>>>();
    finalize_kernel<<<1, 1>>>(out);
}

// round 6
// speedup vs baseline: 2.4911x; 2.4911x over previous
#include <cuda_runtime.h>
#include <math.h>
#include <stdint.h>

// Problem constants
#define B_SZ    4096
#define D_SZ    768
#define HID_SZ  256
#define NC_SZ   200
#define NOLD_SZ 100
#define NNEW_SZ 100
#define EPSILONF 0.05f
#define INV_TAU  10.0f
#define EPSF     1e-8f

// ---------------- device scratch (static: no allocations allowed) -------------
__device__ float g_znorm[B_SZ * D_SZ];
__device__ float g_bnorm[B_SZ * D_SZ];
__device__ float g_f1z[B_SZ * HID_SZ];
__device__ float g_f2z[B_SZ * HID_SZ];
__device__ float g_sim[(size_t)B_SZ * B_SZ];
__device__ float g_attn[(size_t)B_SZ * B_SZ];
__device__ unsigned char g_mask[(size_t)B_SZ * B_SZ];
__device__ float g_meanprobs[NC_SZ];
__device__ float g_losssum;
__device__ float g_nvalid;

// ---------------- helpers -------------------------------------------------------
__device__ __forceinline__ uint32_t smem_u32(const void* p) {
    uint32_t a;
    asm("{ .reg .u64 t; cvta.to.shared.u64 t, %1; cvt.u32.u64 %0, t; }" : "=r"(a) : "l"(p));
    return a;
}
__device__ __forceinline__ float to_tf32(float x) {
    float y;
    asm("cvt.rna.tf32.f32 %0, %1;" : "=f"(y) : "f"(x));
    return y;
}
#define CP_ASYNC16(dst, src) \
    asm volatile("cp.async.cg.shared.global [%0], [%1], 16;" :: "r"(dst), "l"(src) : "memory")
#define CP_COMMIT() asm volatile("cp.async.commit_group;" ::: "memory")
#define CP_WAIT2()  asm volatile("cp.async.wait_group 2;" ::: "memory")

__device__ __forceinline__ void mma_tf32(float* d, const uint32_t* a, const uint32_t* b) {
    asm volatile(
        "mma.sync.aligned.m16n8k8.row.col.f32.tf32.tf32.f32 "
        "{%0,%1,%2,%3}, {%4,%5,%6,%7}, {%8,%9}, {%0,%1,%2,%3};"
        : "+f"(d[0]), "+f"(d[1]), "+f"(d[2]), "+f"(d[3])
        : "r"(a[0]), "r"(a[1]), "r"(a[2]), "r"(a[3]), "r"(b[0]), "r"(b[1]));
}

// ---------------- init ---------------------------------------------------------
__global__ void zero_kernel() {
    int t = threadIdx.x;
    if (t < NC_SZ) g_meanprobs[t] = 0.f;
    if (t == 0) { g_losssum = 0.f; g_nvalid = 0.f; }
}

// ---------------- entropy stats -------------------------------------------------
__global__ void entropy_kernel(const float* __restrict__ logits) {
    __shared__ float sp[NC_SZ];
    int tid = threadIdx.x;
    for (int c = tid; c < NC_SZ; c += blockDim.x) sp[c] = 0.f;
    __syncthreads();

    int warp = tid >> 5, lane = tid & 31;
    int row = blockIdx.x * 8 + warp;
    const float* lrow = logits + (size_t)row * NC_SZ;

    float v[7];
    int cnt = 0;
    float m = -1e30f;
    for (int c = lane; c < NC_SZ; c += 32) {
        float x = lrow[c];
        v[cnt++] = x;
        m = fmaxf(m, x);
    }
#pragma unroll
    for (int o = 16; o > 0; o >>= 1)
        m = fmaxf(m, __shfl_xor_sync(0xffffffffu, m, o));
    float s = 0.f;
    for (int i = 0; i < cnt; i++) { v[i] = __expf(v[i] - m); s += v[i]; }
#pragma unroll
    for (int o = 16; o > 0; o >>= 1)
        s += __shfl_xor_sync(0xffffffffu, s, o);
    float inv = 1.f / s;
    int k = 0;
    for (int c = lane; c < NC_SZ; c += 32)
        atomicAdd(&sp[c], v[k++] * inv);
    __syncthreads();
    for (int c = tid; c < NC_SZ; c += blockDim.x)
        atomicAdd(&g_meanprobs[c], sp[c]);
}

// ---------------- row L2 normalize (output rounded to tf32) --------------------
__global__ void normalize_kernel(const float* __restrict__ zu,
                                 const float* __restrict__ bf) {
    int row = blockIdx.x;
    const float* src = (blockIdx.y == 0) ? zu : bf;
    float* dst = (blockIdx.y == 0) ? g_znorm : g_bnorm;
    const float* srow = src + (size_t)row * D_SZ;
    float* drow = dst + (size_t)row * D_SZ;

    float ss = 0.f;
    for (int k = threadIdx.x; k < D_SZ; k += blockDim.x) {
        float x = srow[k];
        ss = fmaf(x, x, ss);
    }
    __shared__ float red[8];
    __shared__ float s_inv;
    int lane = threadIdx.x & 31, w = threadIdx.x >> 5;
#pragma unroll
    for (int o = 16; o > 0; o >>= 1)
        ss += __shfl_xor_sync(0xffffffffu, ss, o);
    if (lane == 0) red[w] = ss;
    __syncthreads();
    if (threadIdx.x == 0) {
        float t = 0.f;
#pragma unroll
        for (int i = 0; i < 8; i++) t += red[i];
        s_inv = 1.f / fmaxf(sqrtf(t), 1e-12f);
    }
    __syncthreads();
    float inv = s_inv;
    for (int k = threadIdx.x; k < D_SZ; k += blockDim.x)
        drow[k] = to_tf32(srow[k] * inv);
}

// ---------------- tf32 mma.sync GEMM: C = A(MxK) * B(NxK)^T --------------------
// CTA tile 128x128, 8 warps (2x4), warp tile 64x32, K-step 16, 4-stage cp.async.
// SMEM: per stage A[128][20] + B[128][20] floats (pitch 20 => conflict-free frags).
// mode 0: Cf = acc; mode 1: Cmask = (acc>eps && i!=j); mode 2: Cf = tf32(acc+bias)
#define PITCH 20
#define STG_FLOATS (2 * 128 * PITCH)     // 5120 floats = 20480 B
#define NSTAGE 4
#define SMEM_BYTES (NSTAGE * STG_FLOATS * 4)

__device__ __forceinline__ void load_stage(uint32_t sbase,
                                           const float* __restrict__ A,
                                           const float* __restrict__ Bm,
                                           int rowBase, int colBase, int K,
                                           int kt, int t) {
    const int k0 = kt * 16;
#pragma unroll
    for (int h = 0; h < 2; h++) {
        int idx = t + h * 256;           // 0..511
        int row = idx >> 2;              // 0..127
        int kc = (idx & 3) * 4;          // 0,4,8,12
        CP_ASYNC16(sbase + (uint32_t)(row * PITCH + kc) * 4,
                   A + (size_t)(rowBase + row) * K + k0 + kc);
    }
#pragma unroll
    for (int h = 0; h < 2; h++) {
        int idx = t + h * 256;
        int row = idx >> 2;
        int kc = (idx & 3) * 4;
        CP_ASYNC16(sbase + (uint32_t)(128 * PITCH + row * PITCH + kc) * 4,
                   Bm + (size_t)(colBase + row) * K + k0 + kc);
    }
}

__global__ void __launch_bounds__(256, 2)
mma_gemm(const float* __restrict__ A, const float* __restrict__ Bm,
         float* __restrict__ Cf, unsigned char* __restrict__ Cmask,
         const float* __restrict__ bias, int Ntot, int K, int mode) {
    extern __shared__ float smf[];
    const uint32_t su = smem_u32(smf);
    const int t = threadIdx.x;
    const int wid = t >> 5;
    const int lane = t & 31;
    const int r = lane >> 2;             // 0..7
    const int c = lane & 3;              // 0..3
    const int warp_m = (wid & 1) * 64;
    const int warp_n = (wid >> 1) * 32;
    const int rowBase = blockIdx.y * 128;
    const int colBase = blockIdx.x * 128;
    const int KT = K >> 4;

    float acc[4][4][4];
#pragma unroll
    for (int mt = 0; mt < 4; mt++)
#pragma unroll
        for (int nt = 0; nt < 4; nt++)
#pragma unroll
            for (int q = 0; q < 4; q++) acc[mt][nt][q] = 0.f;

    // prologue: 3 stages
#pragma unroll
    for (int s = 0; s < 3; s++) {
        if (s < KT) {
            load_stage(su + s * STG_FLOATS * 4, A, Bm, rowBase, colBase, K, s, t);
            CP_COMMIT();
        }
    }

    for (int kt = 0; kt < KT; kt++) {
        const int s = kt & (NSTAGE - 1);
        CP_WAIT2();
        __syncthreads();

        const float* As = smf + s * STG_FLOATS;
        const float* Bs = As + 128 * PITCH;
#pragma unroll
        for (int kg = 0; kg < 2; kg++) {
            const int kA = kg * 8 + c;
            uint32_t af[4][4], bf[4][2];
#pragma unroll
            for (int mt = 0; mt < 4; mt++) {
                int m = warp_m + mt * 16 + r;
                af[mt][0] = __float_as_uint(As[m * PITCH + kA]);
                af[mt][1] = __float_as_uint(As[(m + 8) * PITCH + kA]);
                af[mt][2] = __float_as_uint(As[m * PITCH + kA + 4]);
                af[mt][3] = __float_as_uint(As[(m + 8) * PITCH + kA + 4]);
            }
#pragma unroll
            for (int nt = 0; nt < 4; nt++) {
                int n = warp_n + nt * 8 + r;
                bf[nt][0] = __float_as_uint(Bs[n * PITCH + kA]);
                bf[nt][1] = __float_as_uint(Bs[n * PITCH + kA + 4]);
            }
#pragma unroll
            for (int mt = 0; mt < 4; mt++)
#pragma unroll
                for (int nt = 0; nt < 4; nt++)
                    mma_tf32(acc[mt][nt], af[mt], bf[nt]);
        }
        __syncthreads();

        const int kn = kt + 3;
        if (kn < KT) {
            load_stage(su + (kn & (NSTAGE - 1)) * STG_FLOATS * 4,
                       A, Bm, rowBase, colBase, K, kn, t);
            CP_COMMIT();
        }
    }

    // ---- epilogue ----
#pragma unroll
    for (int mt = 0; mt < 4; mt++) {
#pragma unroll
        for (int nt = 0; nt < 4; nt++) {
            const int i0 = rowBase + warp_m + mt * 16 + r;
            const int j0 = colBase + warp_n + nt * 8 + 2 * c;
            const float* a4 = acc[mt][nt];
            if (mode == 0) {
                *(float2*)&Cf[(size_t)i0 * Ntot + j0] = make_float2(a4[0], a4[1]);
                *(float2*)&Cf[(size_t)(i0 + 8) * Ntot + j0] = make_float2(a4[2], a4[3]);
            } else if (mode == 1) {
                unsigned char m0 = (a4[0] > EPSILONF && i0 != j0) ? 1 : 0;
                unsigned char m1 = (a4[1] > EPSILONF && i0 != j0 + 1) ? 1 : 0;
                unsigned char m2 = (a4[2] > EPSILONF && (i0 + 8) != j0) ? 1 : 0;
                unsigned char m3 = (a4[3] > EPSILONF && (i0 + 8) != j0 + 1) ? 1 : 0;
                *(uchar2*)&Cmask[(size_t)i0 * Ntot + j0] = make_uchar2(m0, m1);
                *(uchar2*)&Cmask[(size_t)(i0 + 8) * Ntot + j0] = make_uchar2(m2, m3);
            } else {
                float b0 = __ldg(&bias[j0]), b1 = __ldg(&bias[j0 + 1]);
                *(float2*)&Cf[(size_t)i0 * Ntot + j0] =
                    make_float2(to_tf32(a4[0] + b0), to_tf32(a4[1] + b1));
                *(float2*)&Cf[(size_t)(i0 + 8) * Ntot + j0] =
                    make_float2(to_tf32(a4[2] + b0), to_tf32(a4[3] + b1));
            }
        }
    }
}

// ---------------- per-row loss: denom sum + masked online softmax --------------
__global__ void row_loss_kernel() {
    int i = blockIdx.x;
    const float* srow = g_sim + (size_t)i * B_SZ;
    const float* arow = g_attn + (size_t)i * B_SZ;
    const unsigned char* mrow = g_mask + (size_t)i * B_SZ;

    float den = 0.f, m = -1e30f, Z = 0.f, T = 0.f, n = 0.f;
    for (int j = threadIdx.x; j < B_SZ; j += blockDim.x) {
        float s = srow[j];
        if (j != i) den += __expf(s * INV_TAU);
        if (mrow[j]) {
            n += 1.0f;
            float a = arow[j];
            if (a > m) {
                float sc = __expf(m - a);
                Z *= sc; T *= sc; m = a;
            }
            float e = __expf(a - m);
            Z += e;
            T += e * s;
        }
    }

    int lane = threadIdx.x & 31, w = threadIdx.x >> 5;
#pragma unroll
    for (int o = 16; o > 0; o >>= 1) {
        float m2 = __shfl_down_sync(0xffffffffu, m, o);
        float Z2 = __shfl_down_sync(0xffffffffu, Z, o);
        float T2 = __shfl_down_sync(0xffffffffu, T, o);
        float d2 = __shfl_down_sync(0xffffffffu, den, o);
        float n2 = __shfl_down_sync(0xffffffffu, n, o);
        float M = fmaxf(m, m2);
        float s1 = __expf(m - M), s2 = __expf(m2 - M);
        Z = Z * s1 + Z2 * s2;
        T = T * s1 + T2 * s2;
        m = M;
        den += d2;
        n += n2;
    }
    __shared__ float sm_[8], sZ_[8], sT_[8], sd_[8], sn_[8];
    if (lane == 0) { sm_[w] = m; sZ_[w] = Z; sT_[w] = T; sd_[w] = den; sn_[w] = n; }
    __syncthreads();
    if (w == 0) {
        if (lane < 8) { m = sm_[lane]; Z = sZ_[lane]; T = sT_[lane]; den = sd_[lane]; n = sn_[lane]; }
        else { m = -1e30f; Z = 0.f; T = 0.f; den = 0.f; n = 0.f; }
#pragma unroll
        for (int o = 4; o > 0; o >>= 1) {
            float m2 = __shfl_down_sync(0xffffffffu, m, o);
            float Z2 = __shfl_down_sync(0xffffffffu, Z, o);
            float T2 = __shfl_down_sync(0xffffffffu, T, o);
            float d2 = __shfl_down_sync(0xffffffffu, den, o);
            float n2 = __shfl_down_sync(0xffffffffu, n, o);
            float M = fmaxf(m, m2);
            float s1 = __expf(m - M), s2 = __expf(m2 - M);
            Z = Z * s1 + Z2 * s2;
            T = T * s1 + T2 * s2;
            m = M;
            den += d2;
            n += n2;
        }
        if (lane == 0 && n > 0.5f) {
            float loss_i = logf(den + EPSF) - (T / Z) * INV_TAU;
            atomicAdd(&g_losssum, loss_i / n);
            atomicAdd(&g_nvalid, 1.0f);
        }
    }
}

// ---------------- finalize ------------------------------------------------------
__global__ void finalize_kernel(float* out) {
    const double invB = 1.0 / (double)B_SZ;
    double pold = 0.0, pnew = 0.0;
    for (int c = 0; c < NOLD_SZ; c++) pold += (double)g_meanprobs[c] * invB;
    for (int c = NOLD_SZ; c < NC_SZ; c++) pnew += (double)g_meanprobs[c] * invB;
    double loss_inter = pold * log(pold + 1e-8) + pnew * log(pnew + 1e-8) + log(2.0);
    double lo = 0.0;
    for (int c = 0; c < NOLD_SZ; c++) {
        double q = ((double)g_meanprobs[c] * invB) / (pold + 1e-8);
        lo += q * log(q + 1e-8);
    }
    lo += log((double)NOLD_SZ);
    double ln_ = 0.0;
    for (int c = NOLD_SZ; c < NC_SZ; c++) {
        double q = ((double)g_meanprobs[c] * invB) / (pnew + 1e-8);
        ln_ += q * log(q + 1e-8);
    }
    ln_ += log((double)NNEW_SZ);
    double le = loss_inter + lo + ln_;

    float nv = g_nvalid;
    float lc = (nv > 0.f) ? (g_losssum / fmaxf(nv, 1.0f)) : 0.f;
    out[0] = (float)le + lc;
}

// ---------------- launch --------------------------------------------------------
extern "C" void kernel_launch(void* const* d_in, const int* in_sizes, int n_in,
                              void* d_out, int out_size) {
    const float* z_u    = (const float*)d_in[0];
    const float* logits = (const float*)d_in[1];
    const float* base   = (const float*)d_in[4];
    const float* f1w    = (const float*)d_in[5];
    const float* f1b    = (const float*)d_in[6];
    const float* f2w    = (const float*)d_in[7];
    const float* f2b    = (const float*)d_in[8];
    float* out = (float*)d_out;
    (void)in_sizes; (void)n_in; (void)out_size;

    void *pz, *pb, *p1, *p2, *ps, *pa, *pm;
    cudaGetSymbolAddress(&pz, g_znorm);
    cudaGetSymbolAddress(&pb, g_bnorm);
    cudaGetSymbolAddress(&p1, g_f1z);
    cudaGetSymbolAddress(&p2, g_f2z);
    cudaGetSymbolAddress(&ps, g_sim);
    cudaGetSymbolAddress(&pa, g_attn);
    cudaGetSymbolAddress(&pm, g_mask);

    cudaFuncSetAttribute(mma_gemm, cudaFuncAttributeMaxDynamicSharedMemorySize, SMEM_BYTES);

    zero_kernel<<<1, 256>>>();
    entropy_kernel<<<B_SZ / 8, 256>>>(logits);
    normalize_kernel<<<dim3(B_SZ, 2), 256>>>(z_u, base);

    // projections: f1_z/f2_z [4096x256] = z_u @ w^T + b (outputs tf32-rounded)
    mma_gemm<<<dim3(HID_SZ / 128, B_SZ / 128), 256, SMEM_BYTES>>>(
        z_u, f1w, (float*)p1, nullptr, f1b, HID_SZ, D_SZ, 2);
    mma_gemm<<<dim3(HID_SZ / 128, B_SZ / 128), 256, SMEM_BYTES>>>(
        z_u, f2w, (float*)p2, nullptr, f2b, HID_SZ, D_SZ, 2);

    // sim = z_norm @ z_norm^T
    mma_gemm<<<dim3(B_SZ / 128, B_SZ / 128), 256, SMEM_BYTES>>>(
        (float*)pz, (float*)pz, (float*)ps, nullptr, nullptr, B_SZ, D_SZ, 0);
    // mask = (base_norm @ base_norm^T > eps) & ~eye
    mma_gemm<<<dim3(B_SZ / 128, B_SZ / 128), 256, SMEM_BYTES>>>(
        (float*)pb, (float*)pb, nullptr, (unsigned char*)pm, nullptr, B_SZ, D_SZ, 1);
    // attn = f1_z @ f2_z^T (K=256)
    mma_gemm<<<dim3(B_SZ / 128, B_SZ / 128), 256, SMEM_BYTES>>>(
        (float*)p1, (float*)p2, (float*)pa, nullptr, nullptr, B_SZ, HID_SZ, 0);

    row_loss_kernel<<<B_SZ, 256>>>();
    finalize_kernel<<<1, 1>>>(out);
}